// round 14
// baseline (speedup 1.0000x reference)
#include <cuda_runtime.h>
#include <cstdint>

#define BATCH 64
#define HIN   32
#define WIN   32
#define CH    3
#define T_STEPS 2700
#define HID   128
#define PRE_N 32
#define VMAX  256
#define GATES 384
#define IN_DIM 14

#define NT_PRE   1280          // 64 batches x 20 chunks of 135 steps
#define NT_ZERO  96
#define NT_POST  640           // 64 batches x 10 chunks of 270 rows
#define NT_TOTAL (NT_PRE + NT_ZERO + NT_POST)
#define Z4_PER   15872         // 64*3*124*64 / 96

// +8*GATES pad: xg prefetch reload overshoots by up to 3 steps at the tail
__device__ float g_xg[(size_t)BATCH * T_STEPS * GATES + 8 * GATES];
__device__ float g_hs[(size_t)BATCH * T_STEPS * HID];

// cross-CTA state (reset each replay by k_reset)
__device__ volatile int g_prog[BATCH];           // rnn progress (rows) per batch
__device__ volatile int g_preflag[BATCH * 20];   // pre chunk-done flags
__device__ int g_task;                           // worker task counter

__device__ __forceinline__ unsigned long long ffma2(unsigned long long a,
                                                    unsigned long long b,
                                                    unsigned long long c) {
    unsigned long long d;
    asm("fma.rn.f32x2 %0, %1, %2, %3;" : "=l"(d) : "l"(a), "l"(b), "l"(c));
    return d;
}
__device__ __forceinline__ float2 unpack2(unsigned long long v) {
    float2 f;
    asm("mov.b64 {%0, %1}, %2;" : "=f"(f.x), "=f"(f.y) : "l"(v));
    return f;
}
__device__ __forceinline__ float tanh_apx(float x) {
    float y;
    asm("tanh.approx.f32 %0, %1;" : "=f"(y) : "f"(x));
    return y;
}
__device__ __forceinline__ float sigmoid_apx(float x) {
    return fmaf(0.5f, tanh_apx(0.5f * x), 0.5f);
}
__device__ __forceinline__ float sigmoidf_fast(float x) {
    return __fdividef(1.0f, 1.0f + __expf(-x));
}

__global__ void k_dummy(int* p) { if (p) *p = 0; }

// ---------------- reset cross-CTA state ----------------
__global__ void k_reset() {
    int i = blockIdx.x * blockDim.x + threadIdx.x;
    if (i < BATCH) *(int*)&g_prog[i] = 0;
    if (i == BATCH) g_task = 0;
    for (int k = i; k < BATCH * 20; k += gridDim.x * blockDim.x)
        *(int*)&g_preflag[k] = 0;
}

// ---------------- FUSED everything ----------------
// CTAs 0..63   : rnn for batch b; depth-3 in-place xg prefetch (frees ~5 regs
//                vs the depth-4 pipeline that sat exactly at the 128-reg cap);
//                publishes hs progress every 60 steps, gated on pre-chunk flags.
// CTAs 64..147 : persistent workers: pre tasks -> border-zero -> gated post.
#define HSKEW 160
__global__ __launch_bounds__(512, 1) void k_fused(
    const float* __restrict__ x,
    const float* __restrict__ Wpre,
    const float* __restrict__ bpre,
    const float* __restrict__ Wih,
    const float* __restrict__ bih,
    const float* __restrict__ Whh,
    const float* __restrict__ bhh,
    const float* __restrict__ Wpost,
    const float* __restrict__ bpost,
    float* __restrict__ out)
{
    __shared__ __align__(16) float smem_buf[PRE_N * GATES];  // 48KB: WihT | hs+psum | rnn h
    __shared__ int sh_task;

    int tid = threadIdx.x;

    if (blockIdx.x < BATCH) {
        // ================= RNN role =================
        int b = blockIdx.x;
        int j = tid >> 2;
        int s = tid & 3;
        float (*h_sh)[HSKEW] = (float(*)[HSKEW])smem_buf;

        unsigned long long w[3][16];
#pragma unroll
        for (int g = 0; g < 3; g++) {
            const ulonglong2* p = (const ulonglong2*)(Whh + ((size_t)(g * HID + j)) * HID + 32 * s);
#pragma unroll
            for (int k = 0; k < 8; k++) {
                ulonglong2 q = p[k];
                w[g][2 * k]     = q.x;
                w[g][2 * k + 1] = q.y;
            }
        }
        float bn = bhh[2 * HID + j];

        if (tid < HSKEW) { h_sh[0][tid] = 0.f; h_sh[1][tid] = 0.f; }

        // gate: chunk 0 of this batch must be written before first xg loads
        if (tid == 0) {
            while (!g_preflag[b * 20]) __nanosleep(512);
        }
        __syncthreads();
        __threadfence();
        int nextchk = 1;

        int g0 = (s < 3) ? s : 2;
        const float* xgp = g_xg + (size_t)b * T_STEPS * GATES + g0 * HID + j;
        float x0 = xgp[0];
        float x1 = xgp[GATES];
        float x2 = xgp[2 * GATES];
        const float* xp = xgp + 3 * (size_t)GATES;
        float* hsb = g_hs + (size_t)b * T_STEPS * HID + j;
        float hprev = 0.f;
        int sk = (j >> 5) * 4;
        int lq = (tid & 31) & ~3;
        __syncthreads();

        int buf = 0;

#define GRU_STEP(X, OFF)                                                       \
    {                                                                          \
        float xgc = (X);                                                       \
        (X) = xp[OFF]; /* reload for t+3: 3-step in-flight distance */         \
        const ulonglong2* h2 = (const ulonglong2*)(&h_sh[buf][36 * s]);        \
        unsigned long long ar = 0ull, az = 0ull, an = 0ull;                    \
        _Pragma("unroll")                                                      \
        for (int k = 0; k < 8; k++) {                                          \
            ulonglong2 q = h2[k];                                              \
            ar = ffma2(w[0][2 * k],     q.x, ar);                              \
            ar = ffma2(w[0][2 * k + 1], q.y, ar);                              \
            az = ffma2(w[1][2 * k],     q.x, az);                              \
            az = ffma2(w[1][2 * k + 1], q.y, az);                              \
            an = ffma2(w[2][2 * k],     q.x, an);                              \
            an = ffma2(w[2][2 * k + 1], q.y, an);                              \
        }                                                                      \
        float2 p;                                                              \
        p = unpack2(ar); float hr = p.x + p.y; if (s == 0) hr += xgc;          \
        p = unpack2(az); float hz = p.x + p.y; if (s == 1) hz += xgc;          \
        p = unpack2(an); float hn = p.x + p.y; if (s == 3) hn += bn;           \
        float xn = __shfl_sync(0xffffffffu, xgc, lq | 2);                      \
        hr += __shfl_xor_sync(0xffffffffu, hr, 1);                             \
        hr += __shfl_xor_sync(0xffffffffu, hr, 2);                             \
        hz += __shfl_xor_sync(0xffffffffu, hz, 1);                             \
        hz += __shfl_xor_sync(0xffffffffu, hz, 2);                             \
        hn += __shfl_xor_sync(0xffffffffu, hn, 1);                             \
        hn += __shfl_xor_sync(0xffffffffu, hn, 2);                             \
        float r = sigmoid_apx(hr);                                             \
        float z = sigmoid_apx(hz);                                             \
        float n = tanh_apx(fmaf(r, hn, xn));                                   \
        float hnew = fmaf(z, hprev - n, n);                                    \
        hprev = hnew;                                                          \
        buf ^= 1;                                                              \
        if (s == 0) { h_sh[buf][j + sk] = hnew; hsb[0] = hnew; }               \
        hsb += HID;                                                            \
        __syncthreads();                                                       \
    }

        int pubc = 0;
        for (int t = 0; t < T_STEPS; t += 3) {   // 2700 = 900*3
            if (pubc == 0 && t != 0) {           // every 60 steps
                __threadfence();                 // release hs rows < t
                __syncthreads();
                if (tid == 0) {
                    g_prog[b] = t;
                    int tcneed = (t + 65) / 135; // reload reach before next check
                    if (tcneed > 19) tcneed = 19;
                    while (nextchk <= tcneed) {
                        if (g_preflag[b * 20 + nextchk]) nextchk++;
                        else __nanosleep(512);
                    }
                }
                __syncthreads();
                __threadfence();                 // acquire xg rows
            }
            if (++pubc == 20) pubc = 0;
            GRU_STEP(x0, 0);
            GRU_STEP(x1, GATES);
            GRU_STEP(x2, 2 * GATES);
            xp += 3 * (size_t)GATES;
        }
#undef GRU_STEP
        __threadfence();
        __syncthreads();
        if (tid == 0) g_prog[b] = T_STEPS;
    } else {
        // ================= WORKER role =================
        float* WihT  = smem_buf;             // pre phase (12288 floats)
        float* hs_sh = smem_buf;             // post phase (3840 floats)
        float* psum  = smem_buf + 30 * HID;  // post phase (1024 floats)
        int warp = tid >> 5, lane = tid & 31;

        // preload WihT for the pre phase
        for (int i = tid; i < PRE_N * GATES; i += 512) {
            int g = i >> 5, p = i & 31;
            WihT[p * GATES + g] = Wih[i];
        }
        __syncthreads();

        // post-role constants
        int v    = tid & 255;
        int half = tid >> 8;
        unsigned long long w2[32];
        {
            const ulonglong2* wr = (const ulonglong2*)(Wpost + (size_t)v * HID + 64 * half);
#pragma unroll
            for (int k = 0; k < 16; k++) {
                ulonglong2 q = wr[k];
                w2[2 * k]     = q.x;
                w2[2 * k + 1] = q.y;
            }
        }
        float bias = bpost[v];

        for (;;) {
            __syncthreads();
            if (tid == 0) sh_task = atomicAdd(&g_task, 1);
            __syncthreads();
            int tau = sh_task;
            if (tau >= NT_TOTAL) break;

            if (tau < NT_PRE) {
                // ---- PRE task: chunk tc (135 steps) of batch b ----
                int tc = tau >> 6;
                int b  = tau & 63;
                int sbase = tc * 135;
                for (int rr = warp; rr < 135; rr += 16) {
                    int s = sbase + rr;
                    int c  = s % 3;
                    int iw = (s / 3) % 30;
                    int ih = s / 90;

                    float val = 0.f;
                    if (lane < IN_DIM) {
                        if (lane < 12) {
                            int g4 = lane / 3, ch = lane % 3;
                            int dy = (g4 == 3) ? 1 : 0;
                            int dx = (g4 == 3) ? 0 : g4;
                            val = x[(((size_t)(b * CH + ch) * HIN) + (ih + dy)) * WIN + (iw + dx)];
                        } else {
                            int ch = lane - 12;
                            val = (c > ch)
                                ? x[(((size_t)(b * CH + ch) * HIN) + (ih + 1)) * WIN + (iw + 1)]
                                : -1.0f;
                        }
                    }

                    float acc = bpre[lane];
#pragma unroll
                    for (int l = 0; l < IN_DIM; l++)
                        acc = fmaf(Wpre[lane * IN_DIM + l], __shfl_sync(0xffffffffu, val, l), acc);
                    float pre = sigmoidf_fast(acc);

                    float accs[12];
#pragma unroll
                    for (int i = 0; i < 12; i++) {
                        int g = i * 32 + lane;
                        accs[i] = bih[g] + ((i < 8) ? bhh[g] : 0.f);
                    }
#pragma unroll
                    for (int p = 0; p < PRE_N; p++) {
                        float pv = __shfl_sync(0xffffffffu, pre, p);
                        const float* wr = &WihT[p * GATES + lane];
#pragma unroll
                        for (int i = 0; i < 12; i++)
                            accs[i] = fmaf(wr[i * 32], pv, accs[i]);
                    }
                    float* o = g_xg + ((size_t)b * T_STEPS + s) * GATES;
#pragma unroll
                    for (int i = 0; i < 12; i++) o[i * 32 + lane] = accs[i];
                }
                __threadfence();
                __syncthreads();
                if (tid == 0) g_preflag[b * 20 + tc] = 1;
            } else if (tau < NT_PRE + NT_ZERO) {
                // ---- ZERO task: slice of the output border ----
                int z = tau - NT_PRE;
                float4* out4 = (float4*)out;
                int end = (z + 1) * Z4_PER;
                for (int idx = z * Z4_PER + tid; idx < end; idx += 512) {
                    int q = idx & 63;
                    int rest = idx >> 6;
                    int p = rest % 124;
                    int bc = rest / 124;
                    int ih, iw;
                    if (p < 32)      { ih = 0;       iw = p; }
                    else if (p < 64) { ih = 31;      iw = p - 32; }
                    else if (p < 94) { ih = p - 63;  iw = 0; }
                    else             { ih = p - 93;  iw = 31; }
                    out4[((size_t)(bc * HIN + ih) * WIN + iw) * 64 + q] =
                        make_float4(0.f, 0.f, 0.f, 0.f);
                }
            } else {
                // ---- POST task: 270-row output-head chunk, gated on rnn ----
                int pt = tau - NT_PRE - NT_ZERO;
                int c = pt >> 6;       // c-major: gates open in task order
                int b = pt & 63;
                int need = (c + 1) * 270;
                if (tid == 0) {
                    while (g_prog[b] < need) __nanosleep(1024);
                }
                __syncthreads();
                __threadfence();       // acquire hs

                const float* hsb = g_hs + (size_t)b * T_STEPS * HID;
                int s0 = c * 270;
                for (int tile = 0; tile < 9; tile++) {
                    int sbase = s0 + tile * 30;
                    __syncthreads();
                    for (int i = tid; i < 30 * HID; i += 512)
                        hs_sh[i] = hsb[(size_t)sbase * HID + i];
                    __syncthreads();

                    for (int r = 0; r < 30; r += 2) {
                        const ulonglong2* h0 = (const ulonglong2*)(hs_sh + r * HID + 64 * half);
                        const ulonglong2* h1 = (const ulonglong2*)(hs_sh + (r + 1) * HID + 64 * half);
                        unsigned long long a0 = 0ull, a1 = 0ull, c0 = 0ull, c1 = 0ull;
#pragma unroll
                        for (int k = 0; k < 16; k++) {
                            ulonglong2 q0 = h0[k];
                            ulonglong2 q1 = h1[k];
                            a0 = ffma2(w2[2 * k],     q0.x, a0);
                            a1 = ffma2(w2[2 * k + 1], q0.y, a1);
                            c0 = ffma2(w2[2 * k],     q1.x, c0);
                            c1 = ffma2(w2[2 * k + 1], q1.y, c1);
                        }
                        float2 pa = unpack2(a0), pb = unpack2(a1);
                        float o0 = (pa.x + pa.y) + (pb.x + pb.y);
                        pa = unpack2(c0); pb = unpack2(c1);
                        float o1 = (pa.x + pa.y) + (pb.x + pb.y);
                        psum[tid] = o0;
                        psum[512 + tid] = o1;
                        __syncthreads();
                        if (half == 0) {
                            float f0 = psum[tid] + psum[tid + 256] + bias;
                            float f1 = psum[512 + tid] + psum[512 + tid + 256] + bias;
#pragma unroll
                            for (int u = 0; u < 2; u++) {
                                int ss = sbase + r + u;
                                int cc = ss % 3;
                                int iw = (ss / 3) % 30;
                                int ih = ss / 90;
                                size_t idx = ((((size_t)(b * CH + cc) * HIN) + (ih + 1)) * WIN + (iw + 1))
                                             * (size_t)VMAX + v;
                                out[idx] = u ? f1 : f0;
                            }
                        }
                        __syncthreads();
                    }
                }
            }
        }
    }
}

extern "C" void kernel_launch(void* const* d_in, const int* in_sizes, int n_in,
                              void* d_out, int out_size) {
    const float* x      = (const float*)d_in[0];
    const float* W_pre  = (const float*)d_in[1];
    const float* b_pre  = (const float*)d_in[2];
    const float* W_ih   = (const float*)d_in[3];
    const float* b_ih   = (const float*)d_in[4];
    const float* W_hh   = (const float*)d_in[5];
    const float* b_hh   = (const float*)d_in[6];
    const float* W_post = (const float*)d_in[7];
    const float* b_post = (const float*)d_in[8];
    float* out = (float*)d_out;

    k_dummy<<<1, 32>>>(nullptr);
    k_reset<<<4, 512>>>();
    k_fused<<<148, 512>>>(x, W_pre, b_pre, W_ih, b_ih,
                          W_hh, b_hh, W_post, b_post, out);
}

// round 15
// speedup vs baseline: 1.0482x; 1.0482x over previous
#include <cuda_runtime.h>
#include <cstdint>

#define BATCH 64
#define HIN   32
#define WIN   32
#define CH    3
#define T_STEPS 2700
#define HID   128
#define PRE_N 32
#define VMAX  256
#define GATES 384
#define IN_DIM 14

#define NT_PRE   1280          // 64 batches x 20 chunks of 135 steps
#define NT_ZERO  96
#define NT_POST  640           // 64 batches x 10 chunks of 270 rows
#define NT_TOTAL (NT_PRE + NT_ZERO + NT_POST)
#define Z4_PER   15872         // 64*3*124*64 / 96

// +8*GATES pad: xg prefetch pipeline overshoots by up to 4 steps at the tail
__device__ float g_xg[(size_t)BATCH * T_STEPS * GATES + 8 * GATES];
__device__ float g_hs[(size_t)BATCH * T_STEPS * HID];

// cross-CTA state (reset each replay by k_reset)
__device__ volatile int g_prog[BATCH];           // rnn progress (rows) per batch
__device__ volatile int g_preflag[BATCH * 20];   // pre chunk-done flags
__device__ int g_task;                           // worker task counter

__device__ __forceinline__ unsigned long long ffma2(unsigned long long a,
                                                    unsigned long long b,
                                                    unsigned long long c) {
    unsigned long long d;
    asm("fma.rn.f32x2 %0, %1, %2, %3;" : "=l"(d) : "l"(a), "l"(b), "l"(c));
    return d;
}
__device__ __forceinline__ float2 unpack2(unsigned long long v) {
    float2 f;
    asm("mov.b64 {%0, %1}, %2;" : "=f"(f.x), "=f"(f.y) : "l"(v));
    return f;
}
__device__ __forceinline__ float tanh_apx(float x) {
    float y;
    asm("tanh.approx.f32 %0, %1;" : "=f"(y) : "f"(x));
    return y;
}
__device__ __forceinline__ float sigmoid_apx(float x) {
    return fmaf(0.5f, tanh_apx(0.5f * x), 0.5f);
}
__device__ __forceinline__ float sigmoidf_fast(float x) {
    return __fdividef(1.0f, 1.0f + __expf(-x));
}

// ---------------- reset cross-CTA state ----------------
__global__ void k_reset() {
    int i = blockIdx.x * blockDim.x + threadIdx.x;
    if (i < BATCH) *(int*)&g_prog[i] = 0;
    if (i == BATCH) g_task = 0;
    for (int k = i; k < BATCH * 20; k += gridDim.x * blockDim.x)
        *(int*)&g_preflag[k] = 0;
}

// ---------------- FUSED everything ----------------
// CTAs 0..63   : rnn for batch b (round-13 champion body: depth-4 xg pipeline),
//                publishes hs progress every 128 steps, gated on pre-chunk flags.
// CTAs 64..147 : persistent workers: pre tasks -> border-zero -> gated post.
#define HSKEW 160
__global__ __launch_bounds__(512, 1) void k_fused(
    const float* __restrict__ x,
    const float* __restrict__ Wpre,
    const float* __restrict__ bpre,
    const float* __restrict__ Wih,
    const float* __restrict__ bih,
    const float* __restrict__ Whh,
    const float* __restrict__ bhh,
    const float* __restrict__ Wpost,
    const float* __restrict__ bpost,
    float* __restrict__ out)
{
    __shared__ __align__(16) float smem_buf[PRE_N * GATES];  // 48KB: WihT | hs+psum | rnn h
    __shared__ int sh_task;

    int tid = threadIdx.x;

    if (blockIdx.x < BATCH) {
        // ================= RNN role (R13 champion) =================
        int b = blockIdx.x;
        int j = tid >> 2;
        int s = tid & 3;
        float (*h_sh)[HSKEW] = (float(*)[HSKEW])smem_buf;

        unsigned long long w[3][16];
#pragma unroll
        for (int g = 0; g < 3; g++) {
            const ulonglong2* p = (const ulonglong2*)(Whh + ((size_t)(g * HID + j)) * HID + 32 * s);
#pragma unroll
            for (int k = 0; k < 8; k++) {
                ulonglong2 q = p[k];
                w[g][2 * k]     = q.x;
                w[g][2 * k + 1] = q.y;
            }
        }
        float bn = bhh[2 * HID + j];

        if (tid < HSKEW) { h_sh[0][tid] = 0.f; h_sh[1][tid] = 0.f; }

        // gate: chunk 0 of this batch must be written before first xg loads
        if (tid == 0) {
            while (!g_preflag[b * 20]) __nanosleep(512);
        }
        __syncthreads();
        __threadfence();
        int nextchk = 1;

        int g0 = (s < 3) ? s : 2;
        const float* xgp = g_xg + (size_t)b * T_STEPS * GATES + g0 * HID + j;
        float x0 = xgp[0];
        float x1 = xgp[GATES];
        float x2 = xgp[2 * GATES];
        float x3 = xgp[3 * GATES];
        const float* xp = xgp + 4 * (size_t)GATES;
        float* hsb = g_hs + (size_t)b * T_STEPS * HID + j;
        float hprev = 0.f;
        int sk = (j >> 5) * 4;
        int lq = (tid & 31) & ~3;
        __syncthreads();

        int buf = 0;

#define GRU_STEP(XGC)                                                          \
    {                                                                          \
        const ulonglong2* h2 = (const ulonglong2*)(&h_sh[buf][36 * s]);        \
        unsigned long long ar = 0ull, az = 0ull, an = 0ull;                    \
        _Pragma("unroll")                                                      \
        for (int k = 0; k < 8; k++) {                                          \
            ulonglong2 q = h2[k];                                              \
            ar = ffma2(w[0][2 * k],     q.x, ar);                              \
            ar = ffma2(w[0][2 * k + 1], q.y, ar);                              \
            az = ffma2(w[1][2 * k],     q.x, az);                              \
            az = ffma2(w[1][2 * k + 1], q.y, az);                              \
            an = ffma2(w[2][2 * k],     q.x, an);                              \
            an = ffma2(w[2][2 * k + 1], q.y, an);                              \
        }                                                                      \
        float2 p;                                                              \
        p = unpack2(ar); float hr = p.x + p.y; if (s == 0) hr += (XGC);        \
        p = unpack2(az); float hz = p.x + p.y; if (s == 1) hz += (XGC);        \
        p = unpack2(an); float hn = p.x + p.y; if (s == 3) hn += bn;           \
        float xn = __shfl_sync(0xffffffffu, (XGC), lq | 2);                    \
        hr += __shfl_xor_sync(0xffffffffu, hr, 1);                             \
        hr += __shfl_xor_sync(0xffffffffu, hr, 2);                             \
        hz += __shfl_xor_sync(0xffffffffu, hz, 1);                             \
        hz += __shfl_xor_sync(0xffffffffu, hz, 2);                             \
        hn += __shfl_xor_sync(0xffffffffu, hn, 1);                             \
        hn += __shfl_xor_sync(0xffffffffu, hn, 2);                             \
        float r = sigmoid_apx(hr);                                             \
        float z = sigmoid_apx(hz);                                             \
        float n = tanh_apx(fmaf(r, hn, xn));                                   \
        float hnew = fmaf(z, hprev - n, n);                                    \
        hprev = hnew;                                                          \
        buf ^= 1;                                                              \
        if (s == 0) { h_sh[buf][j + sk] = hnew; hsb[0] = hnew; hsb += HID; }   \
        __syncthreads();                                                       \
    }

        for (int t = 0; t < T_STEPS; t += 4) {
            if ((t & 127) == 0 && t != 0) {      // publish/gate every 128 steps
                __threadfence();                 // release hs rows < t
                __syncthreads();
                if (tid == 0) {
                    g_prog[b] = t;
                    int tcneed = (t + 131) / 135;   // reach before next publish
                    if (tcneed > 19) tcneed = 19;
                    while (nextchk <= tcneed) {
                        if (g_preflag[b * 20 + nextchk]) nextchk++;
                        else __nanosleep(512);
                    }
                }
                __syncthreads();
                __threadfence();                 // acquire xg rows
            }
            float n0 = xp[0];
            float n1 = xp[GATES];
            float n2 = xp[2 * GATES];
            float n3 = xp[3 * GATES];
            xp += 4 * (size_t)GATES;
            GRU_STEP(x0); x0 = n0;
            GRU_STEP(x1); x1 = n1;
            GRU_STEP(x2); x2 = n2;
            GRU_STEP(x3); x3 = n3;
        }
#undef GRU_STEP
        __threadfence();
        __syncthreads();
        if (tid == 0) g_prog[b] = T_STEPS;
    } else {
        // ================= WORKER role =================
        float* WihT  = smem_buf;             // pre phase (12288 floats)
        float* hs_sh = smem_buf;             // post phase (3840 floats)
        float* psum  = smem_buf + 30 * HID;  // post phase (1024 floats)
        int warp = tid >> 5, lane = tid & 31;

        // preload WihT for the pre phase
        for (int i = tid; i < PRE_N * GATES; i += 512) {
            int g = i >> 5, p = i & 31;
            WihT[p * GATES + g] = Wih[i];
        }
        __syncthreads();

        // post-role constants
        int v    = tid & 255;
        int half = tid >> 8;
        unsigned long long w2[32];
        {
            const ulonglong2* wr = (const ulonglong2*)(Wpost + (size_t)v * HID + 64 * half);
#pragma unroll
            for (int k = 0; k < 16; k++) {
                ulonglong2 q = wr[k];
                w2[2 * k]     = q.x;
                w2[2 * k + 1] = q.y;
            }
        }
        float bias = bpost[v];

        for (;;) {
            __syncthreads();
            if (tid == 0) sh_task = atomicAdd(&g_task, 1);
            __syncthreads();
            int tau = sh_task;
            if (tau >= NT_TOTAL) break;

            if (tau < NT_PRE) {
                // ---- PRE task: chunk tc (135 steps) of batch b ----
                int tc = tau >> 6;
                int b  = tau & 63;
                int sbase = tc * 135;
                for (int rr = warp; rr < 135; rr += 16) {
                    int s = sbase + rr;
                    int c  = s % 3;
                    int iw = (s / 3) % 30;
                    int ih = s / 90;

                    float val = 0.f;
                    if (lane < IN_DIM) {
                        if (lane < 12) {
                            int g4 = lane / 3, ch = lane % 3;
                            int dy = (g4 == 3) ? 1 : 0;
                            int dx = (g4 == 3) ? 0 : g4;
                            val = x[(((size_t)(b * CH + ch) * HIN) + (ih + dy)) * WIN + (iw + dx)];
                        } else {
                            int ch = lane - 12;
                            val = (c > ch)
                                ? x[(((size_t)(b * CH + ch) * HIN) + (ih + 1)) * WIN + (iw + 1)]
                                : -1.0f;
                        }
                    }

                    float acc = bpre[lane];
#pragma unroll
                    for (int l = 0; l < IN_DIM; l++)
                        acc = fmaf(Wpre[lane * IN_DIM + l], __shfl_sync(0xffffffffu, val, l), acc);
                    float pre = sigmoidf_fast(acc);

                    float accs[12];
#pragma unroll
                    for (int i = 0; i < 12; i++) {
                        int g = i * 32 + lane;
                        accs[i] = bih[g] + ((i < 8) ? bhh[g] : 0.f);
                    }
#pragma unroll
                    for (int p = 0; p < PRE_N; p++) {
                        float pv = __shfl_sync(0xffffffffu, pre, p);
                        const float* wr = &WihT[p * GATES + lane];
#pragma unroll
                        for (int i = 0; i < 12; i++)
                            accs[i] = fmaf(wr[i * 32], pv, accs[i]);
                    }
                    float* o = g_xg + ((size_t)b * T_STEPS + s) * GATES;
#pragma unroll
                    for (int i = 0; i < 12; i++) o[i * 32 + lane] = accs[i];
                }
                __threadfence();
                __syncthreads();
                if (tid == 0) g_preflag[b * 20 + tc] = 1;
            } else if (tau < NT_PRE + NT_ZERO) {
                // ---- ZERO task: slice of the output border ----
                int z = tau - NT_PRE;
                float4* out4 = (float4*)out;
                int end = (z + 1) * Z4_PER;
                for (int idx = z * Z4_PER + tid; idx < end; idx += 512) {
                    int q = idx & 63;
                    int rest = idx >> 6;
                    int p = rest % 124;
                    int bc = rest / 124;
                    int ih, iw;
                    if (p < 32)      { ih = 0;       iw = p; }
                    else if (p < 64) { ih = 31;      iw = p - 32; }
                    else if (p < 94) { ih = p - 63;  iw = 0; }
                    else             { ih = p - 93;  iw = 31; }
                    out4[((size_t)(bc * HIN + ih) * WIN + iw) * 64 + q] =
                        make_float4(0.f, 0.f, 0.f, 0.f);
                }
            } else {
                // ---- POST task: 270-row output-head chunk, gated on rnn ----
                int pt = tau - NT_PRE - NT_ZERO;
                int c = pt >> 6;       // c-major: gates open in task order
                int b = pt & 63;
                int need = (c + 1) * 270;
                if (tid == 0) {
                    while (g_prog[b] < need) __nanosleep(1024);
                }
                __syncthreads();
                __threadfence();       // acquire hs

                const float* hsb = g_hs + (size_t)b * T_STEPS * HID;
                int s0 = c * 270;
                for (int tile = 0; tile < 9; tile++) {
                    int sbase = s0 + tile * 30;
                    __syncthreads();
                    for (int i = tid; i < 30 * HID; i += 512)
                        hs_sh[i] = hsb[(size_t)sbase * HID + i];
                    __syncthreads();

                    for (int r = 0; r < 30; r += 2) {
                        const ulonglong2* h0 = (const ulonglong2*)(hs_sh + r * HID + 64 * half);
                        const ulonglong2* h1 = (const ulonglong2*)(hs_sh + (r + 1) * HID + 64 * half);
                        unsigned long long a0 = 0ull, a1 = 0ull, c0 = 0ull, c1 = 0ull;
#pragma unroll
                        for (int k = 0; k < 16; k++) {
                            ulonglong2 q0 = h0[k];
                            ulonglong2 q1 = h1[k];
                            a0 = ffma2(w2[2 * k],     q0.x, a0);
                            a1 = ffma2(w2[2 * k + 1], q0.y, a1);
                            c0 = ffma2(w2[2 * k],     q1.x, c0);
                            c1 = ffma2(w2[2 * k + 1], q1.y, c1);
                        }
                        float2 pa = unpack2(a0), pb = unpack2(a1);
                        float o0 = (pa.x + pa.y) + (pb.x + pb.y);
                        pa = unpack2(c0); pb = unpack2(c1);
                        float o1 = (pa.x + pa.y) + (pb.x + pb.y);
                        psum[tid] = o0;
                        psum[512 + tid] = o1;
                        __syncthreads();
                        if (half == 0) {
                            float f0 = psum[tid] + psum[tid + 256] + bias;
                            float f1 = psum[512 + tid] + psum[512 + tid + 256] + bias;
#pragma unroll
                            for (int u = 0; u < 2; u++) {
                                int ss = sbase + r + u;
                                int cc = ss % 3;
                                int iw = (ss / 3) % 30;
                                int ih = ss / 90;
                                size_t idx = ((((size_t)(b * CH + cc) * HIN) + (ih + 1)) * WIN + (iw + 1))
                                             * (size_t)VMAX + v;
                                out[idx] = u ? f1 : f0;
                            }
                        }
                        __syncthreads();
                    }
                }
            }
        }
    }
}

extern "C" void kernel_launch(void* const* d_in, const int* in_sizes, int n_in,
                              void* d_out, int out_size) {
    const float* x      = (const float*)d_in[0];
    const float* W_pre  = (const float*)d_in[1];
    const float* b_pre  = (const float*)d_in[2];
    const float* W_ih   = (const float*)d_in[3];
    const float* b_ih   = (const float*)d_in[4];
    const float* W_hh   = (const float*)d_in[5];
    const float* b_hh   = (const float*)d_in[6];
    const float* W_post = (const float*)d_in[7];
    const float* b_post = (const float*)d_in[8];
    float* out = (float*)d_out;

    k_reset<<<4, 512>>>();
    k_fused<<<148, 512>>>(x, W_pre, b_pre, W_ih, b_ih,
                          W_hh, b_hh, W_post, b_post, out);
}